// round 3
// baseline (speedup 1.0000x reference)
#include <cuda_runtime.h>
#include <cstdint>

// FM second-order term:
//   out[b] = sum_e (features[b,:] @ W[:,e])^2  -  sum_f features[b,f]^2 * w2sum[f]
// w2sum[f] = sum_e W[f,e]^2.  B=16384, F=200, E=64, fp32.
//
// R3: cp.async-stage features to smem (kills DRAM latency exposure),
// split-F 2-way for 2x occupancy, single-wave grid (512 blocks, 4/SM).
// Thread = 8 rows x 4 e-cols x 100 features. FFMA2 throughout.

typedef unsigned long long ull;

__device__ __forceinline__ ull pack2(float a, float b) {
    ull r; asm("mov.b64 %0, {%1, %2};" : "=l"(r) : "f"(a), "f"(b)); return r;
}
__device__ __forceinline__ void ffma2(ull &d, ull a, ull b) {
    asm("fma.rn.f32x2 %0, %1, %2, %0;" : "+l"(d) : "l"(a), "l"(b));
}
__device__ __forceinline__ ull fmul2(ull a, ull b) {
    ull r; asm("mul.rn.f32x2 %0, %1, %2;" : "=l"(r) : "l"(a), "l"(b)); return r;
}
__device__ __forceinline__ ull fadd2(ull a, ull b) {
    ull r; asm("add.rn.f32x2 %0, %1, %2;" : "=l"(r) : "l"(a), "l"(b)); return r;
}
__device__ __forceinline__ float lohisum(ull v) {
    float lo, hi; asm("mov.b64 {%0, %1}, %2;" : "=f"(lo), "=f"(hi) : "l"(v)); return lo + hi;
}
__device__ __forceinline__ uint32_t smem_u32(const void* p) {
    return (uint32_t)__cvta_generic_to_shared(p);
}
__device__ __forceinline__ void cp_async16(uint32_t s, const void* g) {
    asm volatile("cp.async.cg.shared.global [%0], [%1], 16;" :: "r"(s), "l"(g));
}

constexpr int F_DIM = 200;
constexpr int E_DIM = 64;
constexpr int THREADS = 128;
constexpr int ROWS_PER_BLOCK = 32;
constexpr int RPT = 8;                    // rows per thread
constexpr int HC = 25;                    // chunks (of 4 features) per fs-half

__global__ void __launch_bounds__(THREADS, 4)
fm_kernel(const float* __restrict__ features,
          const float* __restrict__ W,
          float* __restrict__ out)
{
    __shared__ __align__(16) float fbuf[ROWS_PER_BLOCK][F_DIM];  // 25.6 KB
    __shared__ __align__(16) float w2s[F_DIM];                   // 800 B

    const int tid = threadIdx.x;
    const int eg  = tid & 15;             // e-cols eg*4 .. eg*4+3
    const int fs  = (tid >> 4) & 1;       // feature half
    const int rg  = tid >> 5;             // row group (0..3), rows rg*8..rg*8+7

    // ---- stage this block's 32 feature rows via cp.async (contiguous 25.6KB)
    {
        const float* src = features + (size_t)blockIdx.x * ROWS_PER_BLOCK * F_DIM;
        uint32_t dst = smem_u32(&fbuf[0][0]);
        const int n16 = ROWS_PER_BLOCK * F_DIM / 4;   // 1600 16B packets
        for (int i = tid; i < n16; i += THREADS)
            cp_async16(dst + i * 16, src + i * 4);
        asm volatile("cp.async.commit_group;");
    }

    // ---- w2sum[f] = sum_e W[f,e]^2 (overlaps with cp.async fill)
    for (int f = tid; f < F_DIM; f += THREADS) {
        const float4* wr = (const float4*)(W + f * E_DIM);
        float s = 0.f;
        #pragma unroll
        for (int i = 0; i < E_DIM / 4; ++i) {
            float4 v = wr[i];
            s += v.x * v.x + v.y * v.y + v.z * v.z + v.w * v.w;
        }
        w2s[f] = s;
    }

    asm volatile("cp.async.wait_group 0;" ::: "memory");
    __syncthreads();

    // ---- main loop: 25 chunks of 4 features from this thread's fs-half
    const float* Wq = W + eg * 4;
    const float* fb = &fbuf[rg * RPT][0];

    ull acc[RPT][2];
    #pragma unroll
    for (int r = 0; r < RPT; ++r) { acc[r][0] = 0ull; acc[r][1] = 0ull; }

    #pragma unroll 1
    for (int k = 0; k < HC; ++k) {
        const int c = fs * HC + k;        // global chunk, features c*4..c*4+3

        float4 fv[RPT];
        #pragma unroll
        for (int r = 0; r < RPT; ++r)
            fv[r] = *(const float4*)(fb + r * F_DIM + c * 4);

        ulonglong2 w[4];
        #pragma unroll
        for (int j = 0; j < 4; ++j)
            w[j] = *(const ulonglong2*)(Wq + (c * 4 + j) * E_DIM);

        #pragma unroll
        for (int r = 0; r < RPT; ++r) {
            ull fp;
            fp = pack2(fv[r].x, fv[r].x);
            ffma2(acc[r][0], fp, w[0].x); ffma2(acc[r][1], fp, w[0].y);
            fp = pack2(fv[r].y, fv[r].y);
            ffma2(acc[r][0], fp, w[1].x); ffma2(acc[r][1], fp, w[1].y);
            fp = pack2(fv[r].z, fv[r].z);
            ffma2(acc[r][0], fp, w[2].x); ffma2(acc[r][1], fp, w[2].y);
            fp = pack2(fv[r].w, fv[r].w);
            ffma2(acc[r][0], fp, w[3].x); ffma2(acc[r][1], fp, w[3].y);
        }
    }

    // ---- squared term: (eg,fs) owns a slice of this half's 25 chunks
    // egs 0..8 -> 2 chunks at eg*2; egs 9..15 -> 1 chunk at eg+9
    const int lk0 = (eg < 9) ? eg * 2 : eg + 9;
    const int lkn = (eg < 9) ? 2 : 1;

    ull sq2[RPT];
    #pragma unroll
    for (int r = 0; r < RPT; ++r) sq2[r] = 0ull;

    #pragma unroll
    for (int k = 0; k < 2; ++k) {
        if (k < lkn) {
            const int c = fs * HC + lk0 + k;
            const ull w01 = *(const ull*)(w2s + c * 4);
            const ull w23 = *(const ull*)(w2s + c * 4 + 2);
            #pragma unroll
            for (int r = 0; r < RPT; ++r) {
                float4 fv = *(const float4*)(fb + r * F_DIM + c * 4);
                ull p01 = pack2(fv.x, fv.y);
                ull p23 = pack2(fv.z, fv.w);
                ffma2(sq2[r], fmul2(p01, p01), w01);
                ffma2(sq2[r], fmul2(p23, p23), w23);
            }
        }
    }

    // ---- finalize: combine fs halves, square, subtract, reduce over lanes
    const int rowbase = blockIdx.x * ROWS_PER_BLOCK + rg * RPT;
    #pragma unroll
    for (int r = 0; r < RPT; ++r) {
        ull a0 = fadd2(acc[r][0], __shfl_xor_sync(0xffffffffu, acc[r][0], 16));
        ull a1 = fadd2(acc[r][1], __shfl_xor_sync(0xffffffffu, acc[r][1], 16));
        ull t2 = fadd2(fmul2(a0, a0), fmul2(a1, a1));
        float t = (fs == 0) ? lohisum(t2) : 0.f;   // avoid double-count across fs
        float d = t - lohisum(sq2[r]);
        d += __shfl_xor_sync(0xffffffffu, d, 1);
        d += __shfl_xor_sync(0xffffffffu, d, 2);
        d += __shfl_xor_sync(0xffffffffu, d, 4);
        d += __shfl_xor_sync(0xffffffffu, d, 8);
        d += __shfl_xor_sync(0xffffffffu, d, 16);
        if (eg == 0 && fs == 0) out[rowbase + r] = d;
    }
}

extern "C" void kernel_launch(void* const* d_in, const int* in_sizes, int n_in,
                              void* d_out, int out_size)
{
    const float* features = (const float*)d_in[0];
    const float* W        = (const float*)d_in[1];
    if (n_in >= 2 && in_sizes[0] < in_sizes[1]) {
        features = (const float*)d_in[1];
        W        = (const float*)d_in[0];
    }
    float* out = (float*)d_out;

    const int B = out_size;                      // 16384
    const int blocks = B / ROWS_PER_BLOCK;       // 512 -> single wave at 4/SM
    fm_kernel<<<blocks, THREADS>>>(features, W, out);
}